// round 5
// baseline (speedup 1.0000x reference)
#include <cuda_runtime.h>
#include <cuda_bf16.h>
#include <cstdint>

#define DIM 256
#define KSZ 8
#define MAXC 2048
#define CPB 4          // classes per block in centers kernel

__device__ float g_sq[MAXC];
__device__ float g_pc[MAXC];
__device__ float g_an_total;
__device__ unsigned int g_done;
__device__ __nv_bfloat16 g_hi[MAXC * DIM];
__device__ __nv_bfloat16 g_lo[MAXC * DIM];

__device__ __forceinline__ void cp16(uint32_t smem_addr, const void* gptr) {
    asm volatile("cp.async.cg.shared.global [%0], [%1], 16;\n"
                 :: "r"(smem_addr), "l"(gptr));
}

// ---------------------------------------------------------------------------
// Kernel 1: PERSISTENT block, 4 classes each, cp.async double-buffered.
// 256 threads = 8 warps; warp w owns row w of the current class.
// ---------------------------------------------------------------------------
__global__ void __launch_bounds__(256) centers_kernel(const float* __restrict__ in) {
    int tid  = threadIdx.x;
    int w    = tid >> 5;
    int lane = tid & 31;

    if (blockIdx.x == 0 && tid == 0) { g_an_total = 0.f; g_done = 0u; }

    __shared__ __align__(16) float raw[2][KSZ][DIM];   // 16 KB
    __shared__ float invn[2][KSZ];
    __shared__ float cen[2][DIM];
    __shared__ float redA[2][KSZ];
    __shared__ float redB[2][KSZ];

    int c0 = blockIdx.x * CPB;

    auto load_class = [&](int c, int buf) {
        // 8 KB = 512 float4; thread t moves float4 #t and #(t+256)
        const float4* src = (const float4*)(in + (size_t)c * KSZ * DIM);
        float4* dstbase = (float4*)&raw[buf][0][0];
        cp16((uint32_t)__cvta_generic_to_shared(dstbase + tid),       src + tid);
        cp16((uint32_t)__cvta_generic_to_shared(dstbase + tid + 256), src + tid + 256);
        asm volatile("cp.async.commit_group;\n" ::: "memory");
    };

    load_class(c0, 0);

    for (int it = 0; it < CPB; it++) {
        int c   = c0 + it;
        int buf = it & 1;
        if (it + 1 < CPB) {
            load_class(c + 1, buf ^ 1);
            asm volatile("cp.async.wait_group 1;\n" ::: "memory");
        } else {
            asm volatile("cp.async.wait_group 0;\n" ::: "memory");
        }
        __syncthreads();

        // warp w: row w norm; lane owns dims [lane*8, lane*8+8)
        float v[8];
        {
            float4 a = *(const float4*)&raw[buf][w][lane * 8];
            float4 b = *(const float4*)&raw[buf][w][lane * 8 + 4];
            v[0]=a.x; v[1]=a.y; v[2]=a.z; v[3]=a.w;
            v[4]=b.x; v[5]=b.y; v[6]=b.z; v[7]=b.w;
        }
        float ss = 0.f;
#pragma unroll
        for (int j = 0; j < 8; j++) ss = fmaf(v[j], v[j], ss);
#pragma unroll
        for (int o = 16; o > 0; o >>= 1) ss += __shfl_xor_sync(0xffffffffu, ss, o);
        if (lane == 0) invn[buf][w] = rsqrtf(ss);
        __syncthreads();

        // thread tid owns dim tid
        float cd = 0.f;
#pragma unroll
        for (int k = 0; k < 8; k++) cd = fmaf(raw[buf][k][tid], invn[buf][k], cd);
        cd *= 0.125f;
        cen[buf][tid] = cd;

        __nv_bfloat16 hb = __float2bfloat16(cd);
        g_hi[(size_t)c * DIM + tid] = hb;
        g_lo[(size_t)c * DIM + tid] = __float2bfloat16(cd - __bfloat162float(hb));

        float s2 = cd * cd;
#pragma unroll
        for (int o = 16; o > 0; o >>= 1) s2 += __shfl_xor_sync(0xffffffffu, s2, o);
        if (lane == 0) redA[buf][w] = s2;
        __syncthreads();

        float sqc = 0.f;
#pragma unroll
        for (int k = 0; k < 8; k++) sqc += redA[buf][k];
        if (tid == 0) g_sq[c] = sqc;
        float icn = rsqrtf(sqc);

        float dot = 0.f;
#pragma unroll
        for (int j = 0; j < 8; j++) dot = fmaf(v[j], cen[buf][lane * 8 + j], dot);
#pragma unroll
        for (int o = 16; o > 0; o >>= 1) dot += __shfl_xor_sync(0xffffffffu, dot, o);
        if (lane == 0) {
            float d = invn[buf][w] * icn * dot;
            redB[buf][w] = sqrtf(fmaxf(2.f - 2.f * d, 0.f));
        }
        __syncthreads();
        if (tid == 0) {
            float p = 0.f;
#pragma unroll
            for (int k = 0; k < 8; k++) p += redB[buf][k];
            g_pc[c] = p;
        }
    }
}

// ---------------------------------------------------------------------------
// Kernel 2: upper-triangle Gram GEMM (8 warps, warp tile 32x16, cp.async
// double-buffered), fused hinge, fused FINAL reduction in the last block.
// G = H·H^T + L·H^T (concat K=512).
// ---------------------------------------------------------------------------
__global__ void __launch_bounds__(256) mma_hinge(float* __restrict__ out, int n, int C,
                                                 int nblocks) {
    __shared__ __align__(16) __nv_bfloat16 As[2][64][72];
    __shared__ __align__(16) __nv_bfloat16 Bs[2][64][72];
    __shared__ float sqi_s[64], sqj_s[64];
    __shared__ float warp_sums[8];
    __shared__ int s_last;

    int tid  = threadIdx.x;
    int warp = tid >> 5;
    int lane = tid & 31;

    int NB = C >> 6;
    int bi = 0, rem = blockIdx.x;
    while (rem >= NB - bi) { rem -= NB - bi; bi++; }
    int bj = bi + rem;
    int i0 = bi * 64;
    int j0 = bj * 64;
    bool diag = (bi == bj);

    int wr = warp >> 2;
    int wc = warp & 3;

    float acc[2][2][4] = {};

    auto load_chunk = [&](int kchunk, int buf) {
        const __nv_bfloat16* srcA = (kchunk < 4) ? g_hi : g_lo;
        int k0 = (kchunk & 3) * 64;
#pragma unroll
        for (int vv = 0; vv < 2; vv++) {
            int idx = tid + vv * 256;
            int r = idx >> 3;
            int q = idx & 7;
            cp16((uint32_t)__cvta_generic_to_shared(&As[buf][r][q * 8]),
                 srcA + (size_t)(i0 + r) * DIM + k0 + q * 8);
            cp16((uint32_t)__cvta_generic_to_shared(&Bs[buf][r][q * 8]),
                 g_hi + (size_t)(j0 + r) * DIM + k0 + q * 8);
        }
        asm volatile("cp.async.commit_group;\n" ::: "memory");
    };

    load_chunk(0, 0);
    if (tid < 64)       sqi_s[tid]      = g_sq[i0 + tid];
    else if (tid < 128) sqj_s[tid - 64] = g_sq[j0 + tid - 64];

    for (int kc = 0; kc < 8; kc++) {
        if (kc < 7) {
            load_chunk(kc + 1, (kc + 1) & 1);
            asm volatile("cp.async.wait_group 1;\n" ::: "memory");
        } else {
            asm volatile("cp.async.wait_group 0;\n" ::: "memory");
        }
        __syncthreads();

        int buf = kc & 1;
#pragma unroll
        for (int kk = 0; kk < 64; kk += 16) {
            uint32_t afr[2][4];
#pragma unroll
            for (int mi = 0; mi < 2; mi++) {
                int row = wr * 32 + mi * 16 + (lane & 15);
                int col = kk + (lane >> 4) * 8;
                uint32_t addr = (uint32_t)__cvta_generic_to_shared(&As[buf][row][col]);
                asm volatile("ldmatrix.sync.aligned.m8n8.x4.shared.b16 {%0,%1,%2,%3}, [%4];"
                    : "=r"(afr[mi][0]), "=r"(afr[mi][1]), "=r"(afr[mi][2]), "=r"(afr[mi][3])
                    : "r"(addr));
            }
            uint32_t bfr[2][2];
            {
                int row = wc * 16 + ((lane >> 3) & 1) * 8 + (lane & 7);
                int col = kk + (lane >> 4) * 8;
                uint32_t addr = (uint32_t)__cvta_generic_to_shared(&Bs[buf][row][col]);
                uint32_t r0, r1, r2, r3;
                asm volatile("ldmatrix.sync.aligned.m8n8.x4.shared.b16 {%0,%1,%2,%3}, [%4];"
                    : "=r"(r0), "=r"(r1), "=r"(r2), "=r"(r3) : "r"(addr));
                bfr[0][0] = r0; bfr[0][1] = r2;
                bfr[1][0] = r1; bfr[1][1] = r3;
            }
#pragma unroll
            for (int mi = 0; mi < 2; mi++)
#pragma unroll
                for (int nj = 0; nj < 2; nj++) {
                    asm volatile(
                        "mma.sync.aligned.m16n8k16.row.col.f32.bf16.bf16.f32 "
                        "{%0,%1,%2,%3}, {%4,%5,%6,%7}, {%8,%9}, {%0,%1,%2,%3};"
                        : "+f"(acc[mi][nj][0]), "+f"(acc[mi][nj][1]),
                          "+f"(acc[mi][nj][2]), "+f"(acc[mi][nj][3])
                        : "r"(afr[mi][0]), "r"(afr[mi][1]), "r"(afr[mi][2]), "r"(afr[mi][3]),
                          "r"(bfr[nj][0]), "r"(bfr[nj][1]));
                }
        }
        __syncthreads();
    }

    // hinge epilogue -> grand total
    int qr = lane >> 2;
    int qc = lane & 3;
    float s = 0.f;
#pragma unroll
    for (int mi = 0; mi < 2; mi++)
#pragma unroll
        for (int h = 0; h < 2; h++) {
            int ii = wr * 32 + mi * 16 + h * 8 + qr;
            float sqi = sqi_s[ii];
            int i = i0 + ii;
#pragma unroll
            for (int nj = 0; nj < 2; nj++)
#pragma unroll
                for (int e = 0; e < 2; e++) {
                    int jj = wc * 16 + nj * 8 + qc * 2 + e;
                    int j = j0 + jj;
                    float d2 = sqi + sqj_s[jj] - 2.f * acc[mi][nj][h * 2 + e];
                    float d  = sqrtf(fmaxf(d2, 1e-12f));
                    float hh = fmaxf(0.7f - d, 0.f);
                    if (!diag || i != j) s += hh;
                }
        }
    if (!diag) s *= 2.f;

#pragma unroll
    for (int o = 16; o > 0; o >>= 1) s += __shfl_xor_sync(0xffffffffu, s, o);
    if (lane == 0) warp_sums[warp] = s;
    __syncthreads();
    if (tid == 0) {
        float t = 0.f;
#pragma unroll
        for (int k = 0; k < 8; k++) t += warp_sums[k];
        atomicAdd(&g_an_total, t);
        __threadfence();
        unsigned int v = atomicAdd(&g_done, 1u);
        s_last = (v == (unsigned)(nblocks - 1));
    }
    __syncthreads();

    // last block does the final reduction + output
    if (s_last) {
        int w2 = warp;
        float p = 0.f;
        for (int i = tid; i < C; i += 256) p += g_pc[i];
#pragma unroll
        for (int o = 16; o > 0; o >>= 1) p += __shfl_xor_sync(0xffffffffu, p, o);
        if (lane == 0) warp_sums[w2] = p;
        __syncthreads();
        if (tid == 0) {
            float P = 0.f;
#pragma unroll
            for (int k = 0; k < 8; k++) P += warp_sums[k];
            float pc_mean = P / (float)n;
            float an_mean = g_an_total / ((float)C * (float)(C - 1));
            out[0] = pc_mean + an_mean;
            out[1] = pc_mean;
            out[2] = an_mean;
        }
    }
}

extern "C" void kernel_launch(void* const* d_in, const int* in_sizes, int n_in,
                              void* d_out, int out_size) {
    const float* in = (const float*)d_in[0];
    int n = in_sizes[0] / DIM;   // 8192
    int C = n / KSZ;             // 1024
    int NB = C / 64;             // 16
    int nblocks = NB * (NB + 1) / 2;   // 136

    centers_kernel<<<C / CPB, 256>>>(in);
    mma_hinge<<<nblocks, 256>>>((float*)d_out, n, C, nblocks);
}